// round 3
// baseline (speedup 1.0000x reference)
#include <cuda_runtime.h>
#include <cstdint>

#define BB 8
#define NN 4096
#define MM 4096
#define DD 128

// ---------------- device scratch (no allocations allowed) ----------------
__device__ float g_d0n[(size_t)BB * NN * DD];   // normalized descriptors0
__device__ float g_d1n[(size_t)BB * MM * DD];   // normalized descriptors1
__device__ int   g_m0raw[BB * NN];
__device__ int   g_m1raw[BB * MM];

// ---------------- L2 normalize: one warp per row of 128 floats ----------------
__global__ void norm_kernel(const float* __restrict__ in, float* __restrict__ out, int rows) {
    int row = blockIdx.x * (blockDim.x >> 5) + (threadIdx.x >> 5);
    if (row >= rows) return;
    int lane = threadIdx.x & 31;
    const float4* p = (const float4*)(in + (size_t)row * DD);
    float4 v = p[lane];
    float ss = v.x * v.x + v.y * v.y + v.z * v.z + v.w * v.w;
    #pragma unroll
    for (int o = 16; o > 0; o >>= 1) ss += __shfl_xor_sync(0xffffffffu, ss, o);
    float inv = 1.0f / fmaxf(sqrtf(ss), 1e-12f);
    float4 o4 = make_float4(v.x * inv, v.y * inv, v.z * inv, v.w * inv);
    ((float4*)(out + (size_t)row * DD))[lane] = o4;
}

// ---------------- GEMM: sim[b,n,m] = sum_k d0n[b,n,k]*d1n[b,m,k] ----------------
// 64x64 tile per block, 256 threads, 4x4 microtile, K split into two 64-chunks.
__global__ void gemm_kernel(float* __restrict__ sim) {
    __shared__ float As[64][65];  // [k][row], pad -> conflict-free LDS
    __shared__ float Bs[64][65];

    const int b  = blockIdx.z;
    const int n0 = blockIdx.y * 64;
    const int m0 = blockIdx.x * 64;
    const float* Ab = g_d0n + ((size_t)b * NN + n0) * DD;
    const float* Bb = g_d1n + ((size_t)b * MM + m0) * DD;

    const int tid = threadIdx.x;
    const int tx = tid & 15;
    const int ty = tid >> 4;

    float acc[4][4];
    #pragma unroll
    for (int i = 0; i < 4; i++)
        #pragma unroll
        for (int j = 0; j < 4; j++) acc[i][j] = 0.f;

    #pragma unroll
    for (int kc = 0; kc < 2; kc++) {
        // load 64 rows x 64 k for both tiles: 1024 float4 each, 4 per thread
        #pragma unroll
        for (int i = tid; i < 64 * 16; i += 256) {
            int row = i >> 4, kq = i & 15;
            float4 a = __ldg((const float4*)(Ab + row * DD + kc * 64) + kq);
            As[kq * 4 + 0][row] = a.x; As[kq * 4 + 1][row] = a.y;
            As[kq * 4 + 2][row] = a.z; As[kq * 4 + 3][row] = a.w;
            float4 v = __ldg((const float4*)(Bb + row * DD + kc * 64) + kq);
            Bs[kq * 4 + 0][row] = v.x; Bs[kq * 4 + 1][row] = v.y;
            Bs[kq * 4 + 2][row] = v.z; Bs[kq * 4 + 3][row] = v.w;
        }
        __syncthreads();

        #pragma unroll 16
        for (int k = 0; k < 64; k++) {
            float a0 = As[k][ty];      float a1 = As[k][ty + 16];
            float a2 = As[k][ty + 32]; float a3 = As[k][ty + 48];
            float b0 = Bs[k][tx];      float b1 = Bs[k][tx + 16];
            float b2 = Bs[k][tx + 32]; float b3 = Bs[k][tx + 48];
            acc[0][0] += a0 * b0; acc[0][1] += a0 * b1; acc[0][2] += a0 * b2; acc[0][3] += a0 * b3;
            acc[1][0] += a1 * b0; acc[1][1] += a1 * b1; acc[1][2] += a1 * b2; acc[1][3] += a1 * b3;
            acc[2][0] += a2 * b0; acc[2][1] += a2 * b1; acc[2][2] += a2 * b2; acc[2][3] += a2 * b3;
            acc[3][0] += a3 * b0; acc[3][1] += a3 * b1; acc[3][2] += a3 * b2; acc[3][3] += a3 * b3;
        }
        __syncthreads();
    }

    float* out = sim + ((size_t)b * NN + n0) * MM + m0;
    #pragma unroll
    for (int i = 0; i < 4; i++)
        #pragma unroll
        for (int j = 0; j < 4; j++)
            out[(size_t)(ty + 16 * i) * MM + tx + 16 * j] = acc[i][j];
}

// ---------------- top-2 helpers (tie: lower index wins, matches lax.top_k) ----------------
__device__ __forceinline__ bool better(float va, int ia, float vb, int ib) {
    return (va > vb) || (va == vb && ia < ib);
}

__device__ __forceinline__ void t2_update(float v, int idx, float& v0, int& i0, float& v1, int& i1) {
    if (better(v, idx, v0, i0)) { v1 = v0; i1 = i0; v0 = v; i0 = idx; }
    else if (better(v, idx, v1, i1)) { v1 = v; i1 = idx; }
}

__device__ __forceinline__ int ratio_test(float v0, int i0, float v1) {
    float d0 = 2.0f * (1.0f - v0);
    float d1 = 2.0f * (1.0f - v1);
    const float rt2 = 0.8f * 0.8f;
    const float dt2 = 0.7f * 0.7f;
    bool ok = (d0 <= rt2 * d1) && (d0 <= dt2);
    return ok ? i0 : -1;
}

// ---------------- row top-2: one warp per row, matches0 raw ----------------
__global__ void rowtop2_kernel(const float* __restrict__ sim) {
    int row = blockIdx.x * (blockDim.x >> 5) + (threadIdx.x >> 5);  // 0..B*N-1
    int lane = threadIdx.x & 31;
    const float* p = sim + (size_t)row * MM;

    float v0 = -2.f, v1 = -2.f; int i0 = -1, i1 = -1;
    #pragma unroll 4
    for (int m = lane; m < MM; m += 32) {
        float v = __ldg(p + m);
        t2_update(v, m, v0, i0, v1, i1);
    }
    // butterfly merge of sorted top-2 pairs
    #pragma unroll
    for (int o = 16; o > 0; o >>= 1) {
        float w0 = __shfl_xor_sync(0xffffffffu, v0, o);
        int   j0 = __shfl_xor_sync(0xffffffffu, i0, o);
        float w1 = __shfl_xor_sync(0xffffffffu, v1, o);
        int   j1 = __shfl_xor_sync(0xffffffffu, i1, o);
        if (better(w0, j0, v0, i0)) {
            if (better(v0, i0, w1, j1)) { v1 = v0; i1 = i0; }
            else                        { v1 = w1; i1 = j1; }
            v0 = w0; i0 = j0;
        } else if (better(w0, j0, v1, i1)) { v1 = w0; i1 = j0; }
    }
    if (lane == 0) g_m0raw[row] = ratio_test(v0, i0, v1);
}

// ---------------- column top-2: one thread per column, matches1 raw ----------------
__global__ void coltop2_kernel(const float* __restrict__ sim) {
    int b = blockIdx.y;
    int m = blockIdx.x * blockDim.x + threadIdx.x;
    const float* p = sim + (size_t)b * NN * MM + m;

    float v0 = -2.f, v1 = -2.f; int i0 = -1, i1 = -1;
    #pragma unroll 8
    for (int n = 0; n < NN; n++) {
        float v = __ldg(p + (size_t)n * MM);
        if (v > v0)      { v1 = v0; i1 = i0; v0 = v; i0 = n; }  // increasing n => '>' matches tie rule
        else if (v > v1) { v1 = v; i1 = n; }
    }
    g_m1raw[b * MM + m] = ratio_test(v0, i0, v1);
}

// ---------------- mutual check + write small outputs as float ----------------
__global__ void mutual_kernel(float* __restrict__ out) {
    int i = blockIdx.x * blockDim.x + threadIdx.x;   // 0..B*N-1 (N==M)
    if (i >= BB * NN) return;
    int b = i >> 12, n = i & 4095;

    int a = g_m0raw[i];
    int r0 = (a > -1 && g_m1raw[(b << 12) + a] == n) ? a : -1;
    int c = g_m1raw[i];
    int r1 = (c > -1 && g_m0raw[(b << 12) + c] == n) ? c : -1;

    const int BN = BB * NN;
    out[i]          = (float)r0;                  // matches0
    out[BN + i]     = (float)r1;                  // matches1
    out[2 * BN + i] = (r0 > -1) ? 1.0f : 0.0f;    // mscores0
    out[3 * BN + i] = (r1 > -1) ? 1.0f : 0.0f;    // mscores1
}

// ---------------- launch ----------------
extern "C" void kernel_launch(void* const* d_in, const int* in_sizes, int n_in,
                              void* d_out, int out_size) {
    const float* desc0 = (const float*)d_in[0];
    const float* desc1 = (const float*)d_in[1];
    float* out = (float*)d_out;
    float* sim = out + 4 * BB * NN;   // after matches0, matches1, mscores0, mscores1

    float* d0n; cudaGetSymbolAddress((void**)&d0n, g_d0n);
    float* d1n; cudaGetSymbolAddress((void**)&d1n, g_d1n);

    // 1) normalize: 8 warps/block
    norm_kernel<<<(BB * NN) / 8, 256>>>(desc0, d0n, BB * NN);
    norm_kernel<<<(BB * MM) / 8, 256>>>(desc1, d1n, BB * MM);

    // 2) GEMM -> sim
    dim3 ggrid(MM / 64, NN / 64, BB);
    gemm_kernel<<<ggrid, 256>>>(sim);

    // 3) row top-2 (matches0 raw): 8 warps/block -> 8 rows/block
    rowtop2_kernel<<<(BB * NN) / 8, 256>>>(sim);

    // 4) column top-2 (matches1 raw)
    dim3 cgrid(MM / 256, BB);
    coltop2_kernel<<<cgrid, 256>>>(sim);

    // 5) mutual check + small outputs
    mutual_kernel<<<(BB * NN + 255) / 256, 256>>>(out);
}

// round 10
// speedup vs baseline: 2.1534x; 2.1534x over previous
#include <cuda_runtime.h>
#include <cuda_bf16.h>
#include <cstdint>

#define BB 8
#define NN 4096
#define MM 4096
#define DD 128

// ===================== device scratch (no allocations allowed) =====================
__device__ __nv_bfloat16 g_d0h[(size_t)BB * NN * DD];
__device__ __nv_bfloat16 g_d0l[(size_t)BB * NN * DD];
__device__ __nv_bfloat16 g_d1h[(size_t)BB * MM * DD];
__device__ __nv_bfloat16 g_d1l[(size_t)BB * MM * DD];
__device__ int g_m0raw[BB * NN];
__device__ int g_m1raw[BB * MM];

// ===================== normalize + bf16 hi/lo split =====================
__global__ void norm_kernel(const float* __restrict__ in,
                            __nv_bfloat16* __restrict__ hi,
                            __nv_bfloat16* __restrict__ lo, int rows) {
    int row = blockIdx.x * (blockDim.x >> 5) + (threadIdx.x >> 5);
    if (row >= rows) return;
    int lane = threadIdx.x & 31;
    float4 v = ((const float4*)(in + (size_t)row * DD))[lane];
    float ss = v.x * v.x + v.y * v.y + v.z * v.z + v.w * v.w;
    #pragma unroll
    for (int o = 16; o > 0; o >>= 1) ss += __shfl_xor_sync(0xffffffffu, ss, o);
    float inv = 1.0f / fmaxf(sqrtf(ss), 1e-12f);
    float n0 = v.x * inv, n1 = v.y * inv, n2 = v.z * inv, n3 = v.w * inv;
    __nv_bfloat16 h0 = __float2bfloat16(n0), h1 = __float2bfloat16(n1);
    __nv_bfloat16 h2 = __float2bfloat16(n2), h3 = __float2bfloat16(n3);
    __nv_bfloat16 l0 = __float2bfloat16(n0 - __bfloat162float(h0));
    __nv_bfloat16 l1 = __float2bfloat16(n1 - __bfloat162float(h1));
    __nv_bfloat16 l2 = __float2bfloat16(n2 - __bfloat162float(h2));
    __nv_bfloat16 l3 = __float2bfloat16(n3 - __bfloat162float(h3));
    __nv_bfloat162* ph = (__nv_bfloat162*)(hi + (size_t)row * DD + lane * 4);
    __nv_bfloat162* pl = (__nv_bfloat162*)(lo + (size_t)row * DD + lane * 4);
    ph[0] = __nv_bfloat162(h0, h1); ph[1] = __nv_bfloat162(h2, h3);
    pl[0] = __nv_bfloat162(l0, l1); pl[1] = __nv_bfloat162(l2, l3);
}

// ===================== warp-MMA GEMM (base-ISA HMMA, no tcgen05) =====================
// Tile: 128x128x128 per CTA, 512 threads = 4x4 warps, 32x32 per warp.
// smem: 4 bf16 tiles of 128x128 (A=hi/lo of d0 rows, B=hi/lo of d1 rows), XOR-swizzled.
// sim[n][m] = sum_k A[n][k] * B[m][k]  -> mma.row.col with both tiles [row][K] row-major.

#define SM_AH 0
#define SM_AL 32768
#define SM_BH 65536
#define SM_BL 98304
#define SM_TOTAL 131072

__device__ __forceinline__ uint32_t smem_u32(const void* p) {
    uint32_t a;
    asm("{ .reg .u64 t; cvta.to.shared.u64 t, %1; cvt.u32.u64 %0, t; }" : "=r"(a) : "l"(p));
    return a;
}

#define LDSM_X4(r, a) \
    asm volatile("ldmatrix.sync.aligned.m8n8.x4.shared.b16 {%0,%1,%2,%3}, [%4];" \
        : "=r"((r)[0]), "=r"((r)[1]), "=r"((r)[2]), "=r"((r)[3]) : "r"(a))

#define MMA16816(acc, a, b0_, b1_) \
    asm volatile("mma.sync.aligned.m16n8k16.row.col.f32.bf16.bf16.f32 " \
        "{%0,%1,%2,%3},{%4,%5,%6,%7},{%8,%9},{%0,%1,%2,%3};" \
        : "+f"((acc)[0]), "+f"((acc)[1]), "+f"((acc)[2]), "+f"((acc)[3]) \
        : "r"((a)[0]), "r"((a)[1]), "r"((a)[2]), "r"((a)[3]), "r"(b0_), "r"(b1_))

__global__ void __launch_bounds__(512, 1)
gemm_mma_kernel(float* __restrict__ sim) {
    extern __shared__ char smem[];
    const uint32_t sb = smem_u32(smem);

    const int b  = blockIdx.z;
    const int n0 = blockIdx.y * 128;   // d0 rows (sim rows)
    const int m0 = blockIdx.x * 128;   // d1 rows (sim cols)
    const int tid  = threadIdx.x;
    const int wid  = tid >> 5, lane = tid & 31;
    const int wm   = wid >> 2;         // 0..3 : row-block of 32
    const int wn   = wid & 3;          // 0..3 : col-block of 32

    // ---- cooperative load: 4 contiguous 32KB tiles, swizzled [row*256 + (ch^(row&7))*16]
    {
        const uint4* a_h = (const uint4*)(g_d0h + ((size_t)b * NN + n0) * DD);
        const uint4* a_l = (const uint4*)(g_d0l + ((size_t)b * NN + n0) * DD);
        const uint4* b_h = (const uint4*)(g_d1h + ((size_t)b * MM + m0) * DD);
        const uint4* b_l = (const uint4*)(g_d1l + ((size_t)b * MM + m0) * DD);
        #pragma unroll
        for (int i = tid; i < 2048; i += 512) {
            int row = i >> 4, ch = i & 15;
            uint32_t soff = (uint32_t)(row * 256 + ((ch ^ (row & 7)) << 4));
            *(uint4*)(smem + SM_AH + soff) = __ldg(a_h + i);
            *(uint4*)(smem + SM_AL + soff) = __ldg(a_l + i);
            *(uint4*)(smem + SM_BH + soff) = __ldg(b_h + i);
            *(uint4*)(smem + SM_BL + soff) = __ldg(b_l + i);
        }
    }
    __syncthreads();

    // ---- per-lane ldmatrix row/chunk decomposition
    // A x4 (one m16 tile): lanes 0-15 rows 0..15 chunk c, lanes 16-31 same rows chunk c+1
    const int a_row = wm * 32 + (lane & 15);          // + tm*16
    const int a_cof = (lane >> 4) & 1;
    // B x4 (two n8 tiles = 16 rows): lanes 0-7 r0..7/c, 8-15 r0..7/c+1, 16-23 r8..15/c, 24-31 r8..15/c+1
    const int b_row = wn * 32 + (lane & 7) + ((lane >> 4) << 3);   // + tb*16
    const int b_cof = (lane >> 3) & 1;

    float acc[2][4][4];
    #pragma unroll
    for (int tm = 0; tm < 2; tm++)
        #pragma unroll
        for (int j = 0; j < 4; j++)
            #pragma unroll
            for (int q = 0; q < 4; q++) acc[tm][j][q] = 0.f;

    #pragma unroll
    for (int ks = 0; ks < 8; ks++) {
        uint32_t ah[2][4], al[2][4], bh[2][4], bl[2][4];
        #pragma unroll
        for (int tm = 0; tm < 2; tm++) {
            int row = a_row + tm * 16;
            uint32_t addr = (uint32_t)(row * 256 + (((2 * ks + a_cof) ^ (row & 7)) << 4));
            LDSM_X4(ah[tm], sb + SM_AH + addr);
            LDSM_X4(al[tm], sb + SM_AL + addr);
        }
        #pragma unroll
        for (int tb = 0; tb < 2; tb++) {
            int row = b_row + tb * 16;
            uint32_t addr = (uint32_t)(row * 256 + (((2 * ks + b_cof) ^ (row & 7)) << 4));
            LDSM_X4(bh[tb], sb + SM_BH + addr);
            LDSM_X4(bl[tb], sb + SM_BL + addr);
        }
        #pragma unroll
        for (int tm = 0; tm < 2; tm++)
            #pragma unroll
            for (int j = 0; j < 4; j++) {
                int tb = j >> 1, s = (j & 1) * 2;
                MMA16816(acc[tm][j], ah[tm], bh[tb][s], bh[tb][s + 1]);  // hi*hi
                MMA16816(acc[tm][j], ah[tm], bl[tb][s], bl[tb][s + 1]);  // hi*lo
                MMA16816(acc[tm][j], al[tm], bh[tb][s], bh[tb][s + 1]);  // lo*hi
            }
    }

    // ---- epilogue: direct global stores (float2, 32B-sector coalesced)
    const int g = lane >> 2, c = (lane & 3) * 2;
    #pragma unroll
    for (int tm = 0; tm < 2; tm++) {
        #pragma unroll
        for (int j = 0; j < 4; j++) {
            size_t row0 = (size_t)b * NN + n0 + wm * 32 + tm * 16 + g;
            int col = m0 + wn * 32 + j * 8 + c;
            *(float2*)(sim + row0 * MM + col)       = make_float2(acc[tm][j][0], acc[tm][j][1]);
            *(float2*)(sim + (row0 + 8) * MM + col) = make_float2(acc[tm][j][2], acc[tm][j][3]);
        }
    }
}

// ===================== top-2 helpers (tie: lower index wins) =====================
__device__ __forceinline__ bool better(float va, int ia, float vb, int ib) {
    return (va > vb) || (va == vb && ia < ib);
}
__device__ __forceinline__ void t2_update(float v, int idx, float& v0, int& i0, float& v1, int& i1) {
    if (better(v, idx, v0, i0)) { v1 = v0; i1 = i0; v0 = v; i0 = idx; }
    else if (better(v, idx, v1, i1)) { v1 = v; i1 = idx; }
}
__device__ __forceinline__ int ratio_test(float v0, int i0, float v1) {
    float d0 = 2.0f * (1.0f - v0);
    float d1 = 2.0f * (1.0f - v1);
    bool ok = (d0 <= 0.64f * d1) && (d0 <= 0.49f);
    return ok ? i0 : -1;
}

// ---------------- row top-2: one warp per row (float4 loads) ----------------
__global__ void rowtop2_kernel(const float* __restrict__ sim) {
    int row = blockIdx.x * (blockDim.x >> 5) + (threadIdx.x >> 5);
    int lane = threadIdx.x & 31;
    const float4* p = (const float4*)(sim + (size_t)row * MM);

    float v0 = -2.f, v1 = -2.f; int i0 = -1, i1 = -1;
    #pragma unroll 4
    for (int m4 = lane; m4 < MM / 4; m4 += 32) {
        float4 v = __ldg(p + m4);
        int base = m4 * 4;
        t2_update(v.x, base + 0, v0, i0, v1, i1);
        t2_update(v.y, base + 1, v0, i0, v1, i1);
        t2_update(v.z, base + 2, v0, i0, v1, i1);
        t2_update(v.w, base + 3, v0, i0, v1, i1);
    }
    #pragma unroll
    for (int o = 16; o > 0; o >>= 1) {
        float w0 = __shfl_xor_sync(0xffffffffu, v0, o);
        int   j0 = __shfl_xor_sync(0xffffffffu, i0, o);
        float w1 = __shfl_xor_sync(0xffffffffu, v1, o);
        int   j1 = __shfl_xor_sync(0xffffffffu, i1, o);
        if (better(w0, j0, v0, i0)) {
            if (better(v0, i0, w1, j1)) { v1 = v0; i1 = i0; }
            else                        { v1 = w1; i1 = j1; }
            v0 = w0; i0 = j0;
        } else if (better(w0, j0, v1, i1)) { v1 = w0; i1 = j0; }
    }
    if (lane == 0) g_m0raw[row] = ratio_test(v0, i0, v1);
}

// ---------------- column top-2: one thread per column ----------------
__global__ void coltop2_kernel(const float* __restrict__ sim) {
    int b = blockIdx.y;
    int m = blockIdx.x * blockDim.x + threadIdx.x;
    const float* p = sim + (size_t)b * NN * MM + m;

    float v0 = -2.f, v1 = -2.f; int i0 = -1, i1 = -1;
    #pragma unroll 8
    for (int n = 0; n < NN; n++) {
        float v = __ldg(p + (size_t)n * MM);
        if (v > v0)      { v1 = v0; i1 = i0; v0 = v; i0 = n; }
        else if (v > v1) { v1 = v; i1 = n; }
    }
    g_m1raw[b * MM + m] = ratio_test(v0, i0, v1);
}

// ---------------- mutual check + small outputs ----------------
__global__ void mutual_kernel(float* __restrict__ out) {
    int i = blockIdx.x * blockDim.x + threadIdx.x;
    if (i >= BB * NN) return;
    int b = i >> 12, n = i & 4095;
    int a = g_m0raw[i];
    int r0 = (a > -1 && g_m1raw[(b << 12) + a] == n) ? a : -1;
    int c = g_m1raw[i];
    int r1 = (c > -1 && g_m0raw[(b << 12) + c] == n) ? c : -1;
    const int BN = BB * NN;
    out[i]          = (float)r0;
    out[BN + i]     = (float)r1;
    out[2 * BN + i] = (r0 > -1) ? 1.0f : 0.0f;
    out[3 * BN + i] = (r1 > -1) ? 1.0f : 0.0f;
}

// ===================== launch =====================
extern "C" void kernel_launch(void* const* d_in, const int* in_sizes, int n_in,
                              void* d_out, int out_size) {
    const float* desc0 = (const float*)d_in[0];
    const float* desc1 = (const float*)d_in[1];
    float* out = (float*)d_out;
    float* sim = out + 4 * BB * NN;

    __nv_bfloat16 *d0h, *d0l, *d1h, *d1l;
    cudaGetSymbolAddress((void**)&d0h, g_d0h);
    cudaGetSymbolAddress((void**)&d0l, g_d0l);
    cudaGetSymbolAddress((void**)&d1h, g_d1h);
    cudaGetSymbolAddress((void**)&d1l, g_d1l);

    cudaFuncSetAttribute(gemm_mma_kernel, cudaFuncAttributeMaxDynamicSharedMemorySize, SM_TOTAL);

    norm_kernel<<<(BB * NN) / 8, 256>>>(desc0, d0h, d0l, BB * NN);
    norm_kernel<<<(BB * MM) / 8, 256>>>(desc1, d1h, d1l, BB * MM);

    dim3 ggrid(MM / 128, NN / 128, BB);
    gemm_mma_kernel<<<ggrid, 512, SM_TOTAL>>>(sim);

    rowtop2_kernel<<<(BB * NN) / 8, 256>>>(sim);

    dim3 cgrid(MM / 256, BB);
    coltop2_kernel<<<cgrid, 256>>>(sim);

    mutual_kernel<<<(BB * NN + 255) / 256, 256>>>(out);
}